// round 6
// baseline (speedup 1.0000x reference)
#include <cuda_runtime.h>
#include <math.h>

#define T_TOK 2048
#define H_DIM 512
#define I_DIM 512
#define E_NUM 8
#define KTOP  4

// ---------------- scratch (device globals, no allocs) ----------------
__device__ float g_t[T_TOK * H_DIM];                 // RMSNorm output
__device__ float g_a[(size_t)E_NUM * T_TOK * I_DIM]; // SwiGLU activations per expert slot
__device__ int   g_cnt[E_NUM];                       // tokens routed to each expert
__device__ int   g_tok[E_NUM * T_TOK];               // gathered token ids
__device__ float g_cw [E_NUM * T_TOK];               // combine coefficient per slot
__device__ float g_sumP[E_NUM];                      // sum of gate probs
__device__ float g_imp [E_NUM];                      // sum of gate logits (importance)
__device__ float g_wc  [E_NUM];                      // doubling-weighted counts

// ---------------- init: out = x (residual), zero accumulators ----------------
__global__ void init_kernel(const float* __restrict__ x, float* __restrict__ out) {
    int i = blockIdx.x * blockDim.x + threadIdx.x;
    if (i < (T_TOK * H_DIM) / 4) {
        ((float4*)out)[i] = ((const float4*)x)[i];
    }
    if (blockIdx.x == 0 && threadIdx.x < E_NUM) {
        g_cnt[threadIdx.x]  = 0;
        g_sumP[threadIdx.x] = 0.f;
        g_imp[threadIdx.x]  = 0.f;
        g_wc[threadIdx.x]   = 0.f;
    }
}

// ---------------- RMSNorm ----------------
__global__ void rmsnorm_kernel(const float* __restrict__ x, const float* __restrict__ ns) {
    int t = blockIdx.x, tid = threadIdx.x;            // 128 threads, 4 floats each
    float4 v = ((const float4*)(x + (size_t)t * H_DIM))[tid];
    float ss = v.x * v.x + v.y * v.y + v.z * v.z + v.w * v.w;
    #pragma unroll
    for (int o = 16; o; o >>= 1) ss += __shfl_xor_sync(0xffffffffu, ss, o);
    __shared__ float red[4];
    if ((tid & 31) == 0) red[tid >> 5] = ss;
    __syncthreads();
    float tot = red[0] + red[1] + red[2] + red[3];
    float r = rsqrtf(tot * (1.0f / H_DIM) + 1e-6f);
    float4 s = ((const float4*)ns)[tid];
    float4 o;
    o.x = v.x * r * s.x; o.y = v.y * r * s.y;
    o.z = v.z * r * s.z; o.w = v.w * r * s.w;
    ((float4*)(g_t + (size_t)t * H_DIM))[tid] = o;
}

// ---------------- gating: logits, softmax, top-4, routing lists, aux accumulators ----------------
__global__ void gate_kernel(const float* __restrict__ gw, const float* __restrict__ gb) {
    int t = blockIdx.x;
    int tid = threadIdx.x, w = tid >> 5, lane = tid & 31;   // 256 threads = 8 warps, warp w -> expert w
    __shared__ float sl[E_NUM];
    const float* tr = g_t + (size_t)t * H_DIM;
    float s = 0.f;
    for (int j = lane; j < H_DIM; j += 32) s += tr[j] * gw[w * H_DIM + j];
    #pragma unroll
    for (int o = 16; o; o >>= 1) s += __shfl_xor_sync(0xffffffffu, s, o);
    if (lane == 0) sl[w] = s + gb[w];
    __syncthreads();
    if (tid == 0) {
        float l[E_NUM], p[E_NUM];
        float m = -1e30f;
        #pragma unroll
        for (int e = 0; e < E_NUM; e++) { l[e] = sl[e]; m = fmaxf(m, l[e]); }
        float sum = 0.f;
        #pragma unroll
        for (int e = 0; e < E_NUM; e++) { p[e] = expf(l[e] - m); sum += p[e]; }
        float inv = 1.f / sum;
        #pragma unroll
        for (int e = 0; e < E_NUM; e++) {
            p[e] *= inv;
            atomicAdd(&g_sumP[e], p[e]);
            atomicAdd(&g_imp[e],  l[e]);
        }
        // top-4 (strict > keeps lowest index on ties, matching jax top_k)
        bool used[E_NUM] = {false,false,false,false,false,false,false,false};
        int   idx[KTOP];  float wv[KTOP];  float wsum = 0.f;
        #pragma unroll
        for (int k = 0; k < KTOP; k++) {
            int best = -1; float bv = -1.f;
            #pragma unroll
            for (int e = 0; e < E_NUM; e++)
                if (!used[e] && p[e] > bv) { bv = p[e]; best = e; }
            used[best] = true; idx[k] = best; wv[k] = bv; wsum += bv;
            atomicAdd(&g_wc[best], (float)(16 >> k));   // doubling = 2^(4-k)
        }
        float winv = 1.f / wsum;
        #pragma unroll
        for (int k = 0; k < KTOP; k++) {
            int e = idx[k];
            int slot = atomicAdd(&g_cnt[e], 1);
            g_tok[e * T_TOK + slot] = t;
            g_cw [e * T_TOK + slot] = wv[k] * winv;
        }
    }
}

// ---------------- GEMM1: h = t_gathered @ W1[e]^T (+b1), fused clip+SwiGLU -> g_a ----------------
// Tile: 64 rows x 128 cols, 256 threads (16x16), thread tile 4 rows x 8 cols (4 even/odd col pairs).
__global__ __launch_bounds__(256) void gemm1_kernel(const float* __restrict__ w1,
                                                    const float* __restrict__ b1) {
    int e = blockIdx.z;
    int nt = g_cnt[e];
    int row0 = blockIdx.x * 64;
    if (row0 >= nt) return;
    int colBase = blockIdx.y * 128;   // column in 2I space

    __shared__ float As[16][65];
    __shared__ float Bs[16][132];
    int tid = threadIdx.x, tx = tid & 15, ty = tid >> 4;
    const float* W = w1 + (size_t)e * (2 * I_DIM) * H_DIM;

    int tokA[4];
    #pragma unroll
    for (int j = 0; j < 4; j++) {
        int slot = row0 + ty + 16 * j;
        tokA[j] = g_tok[e * T_TOK + (slot < nt ? slot : nt - 1)];
    }

    float acc[4][8];
    #pragma unroll
    for (int i = 0; i < 4; i++)
        #pragma unroll
        for (int c = 0; c < 8; c++) acc[i][c] = 0.f;

    for (int k0 = 0; k0 < H_DIM; k0 += 16) {
        #pragma unroll
        for (int j = 0; j < 4; j++)
            As[tx][ty + 16 * j] = g_t[(size_t)tokA[j] * H_DIM + k0 + tx];
        #pragma unroll
        for (int j = 0; j < 8; j++)
            Bs[tx][ty + 16 * j] = W[(size_t)(colBase + ty + 16 * j) * H_DIM + k0 + tx];
        __syncthreads();
        #pragma unroll
        for (int k = 0; k < 16; k++) {
            float ra[4];
            #pragma unroll
            for (int i = 0; i < 4; i++) ra[i] = As[k][ty + 16 * i];
            float rb[8];
            #pragma unroll
            for (int g = 0; g < 4; g++) {
                rb[2 * g]     = Bs[k][32 * g + 2 * tx];
                rb[2 * g + 1] = Bs[k][32 * g + 2 * tx + 1];
            }
            #pragma unroll
            for (int i = 0; i < 4; i++)
                #pragma unroll
                for (int c = 0; c < 8; c++) acc[i][c] += ra[i] * rb[c];
        }
        __syncthreads();
    }

    const float* bias = b1 + (size_t)e * 2 * I_DIM;
    #pragma unroll
    for (int i = 0; i < 4; i++) {
        int slot = row0 + ty + 16 * i;
        if (slot >= nt) continue;
        float* arow = g_a + ((size_t)e * T_TOK + slot) * I_DIM + (colBase >> 1);
        #pragma unroll
        for (int g = 0; g < 4; g++) {
            int c = 32 * g + 2 * tx;
            float hg = acc[i][2 * g]     + bias[colBase + c];
            float hl = acc[i][2 * g + 1] + bias[colBase + c + 1];
            hg = fminf(fmaxf(hg, -7.f), 7.f);
            hl = fminf(fmaxf(hl, -7.f), 7.f);
            float sg = 1.f / (1.f + expf(-1.702f * hg));
            arow[16 * g + tx] = hg * sg + (hl + 1.f);
        }
    }
}

// ---------------- GEMM2: y = a @ W2[e]^T (+b2); out += coeff*y via atomics ----------------
__global__ __launch_bounds__(256) void gemm2_kernel(const float* __restrict__ w2,
                                                    const float* __restrict__ b2,
                                                    float* __restrict__ out) {
    int e = blockIdx.z;
    int nt = g_cnt[e];
    int row0 = blockIdx.x * 64;
    if (row0 >= nt) return;
    int colBase = blockIdx.y * 128;

    __shared__ float As[16][65];
    __shared__ float Bs[16][132];
    int tid = threadIdx.x, tx = tid & 15, ty = tid >> 4;
    const float* A = g_a + (size_t)e * T_TOK * I_DIM;
    const float* W = w2 + (size_t)e * H_DIM * I_DIM;

    int rowA[4];
    #pragma unroll
    for (int j = 0; j < 4; j++) {
        int slot = row0 + ty + 16 * j;
        rowA[j] = (slot < nt ? slot : nt - 1);
    }

    float acc[4][8];
    #pragma unroll
    for (int i = 0; i < 4; i++)
        #pragma unroll
        for (int c = 0; c < 8; c++) acc[i][c] = 0.f;

    for (int k0 = 0; k0 < I_DIM; k0 += 16) {
        #pragma unroll
        for (int j = 0; j < 4; j++)
            As[tx][ty + 16 * j] = A[(size_t)rowA[j] * I_DIM + k0 + tx];
        #pragma unroll
        for (int j = 0; j < 8; j++)
            Bs[tx][ty + 16 * j] = W[(size_t)(colBase + ty + 16 * j) * I_DIM + k0 + tx];
        __syncthreads();
        #pragma unroll
        for (int k = 0; k < 16; k++) {
            float ra[4];
            #pragma unroll
            for (int i = 0; i < 4; i++) ra[i] = As[k][ty + 16 * i];
            float rb[8];
            #pragma unroll
            for (int g = 0; g < 4; g++) {
                rb[2 * g]     = Bs[k][32 * g + 2 * tx];
                rb[2 * g + 1] = Bs[k][32 * g + 2 * tx + 1];
            }
            #pragma unroll
            for (int i = 0; i < 4; i++)
                #pragma unroll
                for (int c = 0; c < 8; c++) acc[i][c] += ra[i] * rb[c];
        }
        __syncthreads();
    }

    const float* bias = b2 + (size_t)e * H_DIM;
    #pragma unroll
    for (int i = 0; i < 4; i++) {
        int slot = row0 + ty + 16 * i;
        if (slot >= nt) continue;
        int token = g_tok[e * T_TOK + slot];
        float cw  = g_cw [e * T_TOK + slot];
        float* orow = out + (size_t)token * H_DIM;
        #pragma unroll
        for (int g = 0; g < 4; g++) {
            int c = colBase + 32 * g + 2 * tx;
            atomicAdd(&orow[c],     cw * (acc[i][2 * g]     + bias[c]));
            atomicAdd(&orow[c + 1], cw * (acc[i][2 * g + 1] + bias[c + 1]));
        }
    }
}

// ---------------- aux loss ----------------
__global__ void finalize_kernel(float* __restrict__ out, int out_size) {
    if (threadIdx.x == 0 && blockIdx.x == 0) {
        float load = 0.f;
        #pragma unroll
        for (int e = 0; e < E_NUM; e++) {
            float P = g_sumP[e] / (float)T_TOK;
            float D = g_wc[e] / (float)(T_TOK * KTOP);
            load += P * D;
        }
        load *= 0.01f * (float)E_NUM;           // W_LOAD * E
        float m = 0.f;
        #pragma unroll
        for (int e = 0; e < E_NUM; e++) m += g_imp[e];
        m *= (1.f / E_NUM);
        float v = 0.f;
        #pragma unroll
        for (int e = 0; e < E_NUM; e++) { float d = g_imp[e] - m; v += d * d; }
        v *= (1.f / (E_NUM - 1));               // ddof=1
        float cv = sqrtf(v) / (m + 1e-6f);
        out[out_size - 1] = 1.0f * (load + 0.01f * cv * cv);   // W_AUX*(load + W_IMP*cv^2)
    }
}

// ---------------- launch ----------------
extern "C" void kernel_launch(void* const* d_in, const int* in_sizes, int n_in,
                              void* d_out, int out_size) {
    const float* x  = (const float*)d_in[0];
    const float* ns = (const float*)d_in[1];
    const float* gw = (const float*)d_in[2];
    const float* gb = (const float*)d_in[3];
    const float* w1 = (const float*)d_in[4];
    const float* b1 = (const float*)d_in[5];
    const float* w2 = (const float*)d_in[6];
    const float* b2 = (const float*)d_in[7];
    float* out = (float*)d_out;

    init_kernel<<<(T_TOK * H_DIM / 4 + 255) / 256, 256>>>(x, out);
    rmsnorm_kernel<<<T_TOK, 128>>>(x, ns);
    gate_kernel<<<T_TOK, 256>>>(gw, gb);
    dim3 g1(T_TOK / 64, (2 * I_DIM) / 128, E_NUM);
    gemm1_kernel<<<g1, 256>>>(w1, b1);
    dim3 g2(T_TOK / 64, H_DIM / 128, E_NUM);
    gemm2_kernel<<<g2, 256>>>(w2, b2, out);
    finalize_kernel<<<1, 32>>>(out, out_size);
}

// round 8
// speedup vs baseline: 3.3729x; 3.3729x over previous
#include <cuda_runtime.h>
#include <cuda_fp16.h>
#include <math.h>

#define T_TOK 2048
#define H_DIM 512
#define I_DIM 512
#define E_NUM 8
#define KTOP  4
#define BK    64
#define KPAD  8

// ---------------- scratch (device globals, no allocs) ----------------
__device__ float  g_t  [T_TOK * H_DIM];                       // RMSNorm out fp32 (gate)
__device__ __half g_th [T_TOK * H_DIM];                       // RMSNorm out fp16 (gemm1 A)
__device__ __half g_w1h[(size_t)E_NUM * 2 * I_DIM * H_DIM];   // W1 fp16
__device__ __half g_w2h[(size_t)E_NUM * H_DIM * I_DIM];       // W2 fp16
__device__ __half g_ah [(size_t)E_NUM * T_TOK * I_DIM];       // SwiGLU activations fp16
__device__ float  g_y  [(size_t)E_NUM * T_TOK * H_DIM];       // weighted expert outputs fp32
__device__ int    g_cnt[E_NUM];
__device__ int    g_tok[E_NUM * T_TOK];
__device__ float  g_cw [E_NUM * T_TOK];
__device__ int    g_slot[T_TOK * KTOP];                       // token -> 4 global slot ids
__device__ float  g_sumP[E_NUM];
__device__ float  g_imp [E_NUM];
__device__ float  g_wc  [E_NUM];

// ---------------- PTX helpers (base compute_103 target only: HMMA + LDSM) ----------------
__device__ __forceinline__ unsigned smem_u32(const void* p) {
    unsigned r;
    asm("{ .reg .u64 t; cvta.to.shared.u64 t, %1; cvt.u32.u64 %0, t; }" : "=r"(r) : "l"(p));
    return r;
}

__device__ __forceinline__ void ldsm_x4(unsigned& r0, unsigned& r1, unsigned& r2, unsigned& r3,
                                        unsigned addr) {
    asm volatile("ldmatrix.sync.aligned.m8n8.x4.shared.b16 {%0,%1,%2,%3}, [%4];"
                 : "=r"(r0), "=r"(r1), "=r"(r2), "=r"(r3) : "r"(addr));
}
__device__ __forceinline__ void ldsm_x2(unsigned& r0, unsigned& r1, unsigned addr) {
    asm volatile("ldmatrix.sync.aligned.m8n8.x2.shared.b16 {%0,%1}, [%2];"
                 : "=r"(r0), "=r"(r1) : "r"(addr));
}
__device__ __forceinline__ void hmma(float* c, const unsigned* a, const unsigned* b) {
    asm volatile("mma.sync.aligned.m16n8k16.row.col.f32.f16.f16.f32 "
                 "{%0,%1,%2,%3}, {%4,%5,%6,%7}, {%8,%9}, {%0,%1,%2,%3};"
                 : "+f"(c[0]), "+f"(c[1]), "+f"(c[2]), "+f"(c[3])
                 : "r"(a[0]), "r"(a[1]), "r"(a[2]), "r"(a[3]), "r"(b[0]), "r"(b[1]));
}

// ---------------- init: zero accumulators ----------------
__global__ void init_kernel() {
    if (threadIdx.x < E_NUM) {
        g_cnt[threadIdx.x]  = 0;
        g_sumP[threadIdx.x] = 0.f;
        g_imp[threadIdx.x]  = 0.f;
        g_wc[threadIdx.x]   = 0.f;
    }
}

// ---------------- fp32 -> fp16 weight conversion ----------------
__global__ void conv_kernel(const float* __restrict__ s, __half* __restrict__ d, int n4) {
    int i = blockIdx.x * blockDim.x + threadIdx.x;
    if (i < n4) {
        float4 v = ((const float4*)s)[i];
        ((__half2*)d)[2 * i]     = __floats2half2_rn(v.x, v.y);
        ((__half2*)d)[2 * i + 1] = __floats2half2_rn(v.z, v.w);
    }
}

// ---------------- RMSNorm (fp32 + fp16 outputs) ----------------
__global__ void rmsnorm_kernel(const float* __restrict__ x, const float* __restrict__ ns) {
    int t = blockIdx.x, tid = threadIdx.x;            // 128 threads, 4 floats each
    float4 v = ((const float4*)(x + (size_t)t * H_DIM))[tid];
    float ss = v.x * v.x + v.y * v.y + v.z * v.z + v.w * v.w;
    #pragma unroll
    for (int o = 16; o; o >>= 1) ss += __shfl_xor_sync(0xffffffffu, ss, o);
    __shared__ float red[4];
    if ((tid & 31) == 0) red[tid >> 5] = ss;
    __syncthreads();
    float tot = red[0] + red[1] + red[2] + red[3];
    float r = rsqrtf(tot * (1.0f / H_DIM) + 1e-6f);
    float4 s = ((const float4*)ns)[tid];
    float4 o;
    o.x = v.x * r * s.x; o.y = v.y * r * s.y;
    o.z = v.z * r * s.z; o.w = v.w * r * s.w;
    ((float4*)(g_t + (size_t)t * H_DIM))[tid] = o;
    __half2* th = (__half2*)(g_th + (size_t)t * H_DIM);
    th[2 * tid]     = __floats2half2_rn(o.x, o.y);
    th[2 * tid + 1] = __floats2half2_rn(o.z, o.w);
}

// ---------------- gating (fp32, identical routing to passing kernel) ----------------
__global__ void gate_kernel(const float* __restrict__ gw, const float* __restrict__ gb) {
    int t = blockIdx.x;
    int tid = threadIdx.x, w = tid >> 5, lane = tid & 31;
    __shared__ float sl[E_NUM];
    const float* tr = g_t + (size_t)t * H_DIM;
    float s = 0.f;
    for (int j = lane; j < H_DIM; j += 32) s += tr[j] * gw[w * H_DIM + j];
    #pragma unroll
    for (int o = 16; o; o >>= 1) s += __shfl_xor_sync(0xffffffffu, s, o);
    if (lane == 0) sl[w] = s + gb[w];
    __syncthreads();
    if (tid == 0) {
        float l[E_NUM], p[E_NUM];
        float m = -1e30f;
        #pragma unroll
        for (int e = 0; e < E_NUM; e++) { l[e] = sl[e]; m = fmaxf(m, l[e]); }
        float sum = 0.f;
        #pragma unroll
        for (int e = 0; e < E_NUM; e++) { p[e] = expf(l[e] - m); sum += p[e]; }
        float inv = 1.f / sum;
        #pragma unroll
        for (int e = 0; e < E_NUM; e++) {
            p[e] *= inv;
            atomicAdd(&g_sumP[e], p[e]);
            atomicAdd(&g_imp[e],  l[e]);
        }
        bool used[E_NUM] = {false,false,false,false,false,false,false,false};
        int   idx[KTOP];  float wv[KTOP];  float wsum = 0.f;
        #pragma unroll
        for (int k = 0; k < KTOP; k++) {
            int best = -1; float bv = -1.f;
            #pragma unroll
            for (int e = 0; e < E_NUM; e++)
                if (!used[e] && p[e] > bv) { bv = p[e]; best = e; }
            used[best] = true; idx[k] = best; wv[k] = bv; wsum += bv;
            atomicAdd(&g_wc[best], (float)(16 >> k));
        }
        float winv = 1.f / wsum;
        #pragma unroll
        for (int k = 0; k < KTOP; k++) {
            int e = idx[k];
            int slot = atomicAdd(&g_cnt[e], 1);
            g_tok[e * T_TOK + slot] = t;
            g_cw [e * T_TOK + slot] = wv[k] * winv;
            g_slot[t * KTOP + k] = e * T_TOK + slot;
        }
    }
}

// ---------------- GEMM1 (mma.sync): h = gather(t) @ W1[e]^T (+b1), SwiGLU -> g_ah fp16 ----------
// Block 128x128, K in 8 chunks of 64. 8 warps (2m x 4n), warp tile 64x32 via m16n8k16.
__global__ __launch_bounds__(256) void gemm1_tc(const float* __restrict__ b1) {
    int e = blockIdx.z;
    int nt = g_cnt[e];
    int row0 = blockIdx.x * 128;
    if (row0 >= nt) return;
    int colBase = blockIdx.y * 128;                 // column in 2I space

    __shared__ __half As[128][BK + KPAD];
    __shared__ __half Bs[128][BK + KPAD];

    int tid = threadIdx.x, lane = tid & 31, wid = tid >> 5;
    int wm = wid & 1, wn = wid >> 1;               // warp at (wm*64, wn*32)

    // global staging: each thread loads 4 uint4 for A and 4 for B per chunk
    int lrow = tid >> 1;                            // 0..127
    int lcol = (tid & 1) * 32;                      // half offset within chunk
    const __half* srcA;
    const __half* srcB;
    {
        int slot = row0 + lrow; if (slot >= nt) slot = nt - 1;
        int token = g_tok[e * T_TOK + slot];
        srcA = g_th + (size_t)token * H_DIM + lcol;
        srcB = g_w1h + ((size_t)e * (2 * I_DIM) + colBase + lrow) * H_DIM + lcol;
    }

    float acc[4][4][4];
    #pragma unroll
    for (int mi = 0; mi < 4; mi++)
        #pragma unroll
        for (int ni = 0; ni < 4; ni++)
            #pragma unroll
            for (int j = 0; j < 4; j++) acc[mi][ni][j] = 0.f;

    uint4 ra[4], rb[4];
    #pragma unroll
    for (int i = 0; i < 4; i++) {
        ra[i] = ((const uint4*)srcA)[i];
        rb[i] = ((const uint4*)srcB)[i];
    }

    // precompute ldmatrix smem addresses (chunk-invariant)
    unsigned aAddr[4], bAddr[4];
    #pragma unroll
    for (int mi = 0; mi < 4; mi++)
        aAddr[mi] = smem_u32(&As[wm * 64 + mi * 16 + (lane & 15)][(lane >> 4) * 8]);
    #pragma unroll
    for (int ni = 0; ni < 4; ni++)
        bAddr[ni] = smem_u32(&Bs[wn * 32 + ni * 8 + (lane & 7)][((lane >> 3) & 1) * 8]);

    for (int ch = 0; ch < 8; ch++) {
        __syncthreads();
        #pragma unroll
        for (int i = 0; i < 4; i++) {
            *(uint4*)&As[lrow][lcol + i * 8] = ra[i];
            *(uint4*)&Bs[lrow][lcol + i * 8] = rb[i];
        }
        __syncthreads();
        if (ch < 7) {
            const uint4* pa = (const uint4*)(srcA + (ch + 1) * BK);
            const uint4* pb = (const uint4*)(srcB + (ch + 1) * BK);
            #pragma unroll
            for (int i = 0; i < 4; i++) { ra[i] = pa[i]; rb[i] = pb[i]; }
        }
        #pragma unroll
        for (int ks = 0; ks < 4; ks++) {
            unsigned a[4][4], b[4][2];
            #pragma unroll
            for (int mi = 0; mi < 4; mi++)
                ldsm_x4(a[mi][0], a[mi][1], a[mi][2], a[mi][3], aAddr[mi] + ks * 32);
            #pragma unroll
            for (int ni = 0; ni < 4; ni++)
                ldsm_x2(b[ni][0], b[ni][1], bAddr[ni] + ks * 32);
            #pragma unroll
            for (int mi = 0; mi < 4; mi++)
                #pragma unroll
                for (int ni = 0; ni < 4; ni++)
                    hmma(acc[mi][ni], a[mi], b[ni]);
        }
    }

    // epilogue: fused bias + clip + SwiGLU; c0(even col)/c1(odd col) pair in-thread
    const float* bias = b1 + e * (2 * I_DIM) + colBase + wn * 32;
    int q  = lane & 3;
    int rr = lane >> 2;
    #pragma unroll
    for (int mi = 0; mi < 4; mi++) {
        #pragma unroll
        for (int h = 0; h < 2; h++) {
            int slot = row0 + wm * 64 + mi * 16 + rr + h * 8;
            if (slot < nt) {
                __half* arow = g_ah + ((size_t)e * T_TOK + slot) * I_DIM
                             + (colBase >> 1) + wn * 16;
                #pragma unroll
                for (int ni = 0; ni < 4; ni++) {
                    float hg = acc[mi][ni][h * 2]     + bias[ni * 8 + q * 2];
                    float hl = acc[mi][ni][h * 2 + 1] + bias[ni * 8 + q * 2 + 1];
                    hg = fminf(fmaxf(hg, -7.f), 7.f);
                    hl = fminf(fmaxf(hl, -7.f), 7.f);
                    float sg = 1.f / (1.f + __expf(-1.702f * hg));
                    arow[ni * 4 + q] = __float2half_rn(hg * sg + (hl + 1.f));
                }
            }
        }
    }
}

// ---------------- GEMM2 (mma.sync): y = a @ W2[e]^T; g_y = cw*(y + b2) ----------------
__global__ __launch_bounds__(256) void gemm2_tc(const float* __restrict__ b2) {
    int e = blockIdx.z;
    int nt = g_cnt[e];
    int row0 = blockIdx.x * 128;
    if (row0 >= nt) return;
    int colBase = blockIdx.y * 128;                 // column in H space

    __shared__ __half As[128][BK + KPAD];
    __shared__ __half Bs[128][BK + KPAD];

    int tid = threadIdx.x, lane = tid & 31, wid = tid >> 5;
    int wm = wid & 1, wn = wid >> 1;

    int lrow = tid >> 1;
    int lcol = (tid & 1) * 32;
    const __half* srcA;
    const __half* srcB;
    {
        int slot = row0 + lrow; if (slot >= nt) slot = nt - 1;
        srcA = g_ah + ((size_t)e * T_TOK + slot) * I_DIM + lcol;
        srcB = g_w2h + ((size_t)e * H_DIM + colBase + lrow) * I_DIM + lcol;
    }

    float acc[4][4][4];
    #pragma unroll
    for (int mi = 0; mi < 4; mi++)
        #pragma unroll
        for (int ni = 0; ni < 4; ni++)
            #pragma unroll
            for (int j = 0; j < 4; j++) acc[mi][ni][j] = 0.f;

    uint4 ra[4], rb[4];
    #pragma unroll
    for (int i = 0; i < 4; i++) {
        ra[i] = ((const uint4*)srcA)[i];
        rb[i] = ((const uint4*)srcB)[i];
    }

    unsigned aAddr[4], bAddr[4];
    #pragma unroll
    for (int mi = 0; mi < 4; mi++)
        aAddr[mi] = smem_u32(&As[wm * 64 + mi * 16 + (lane & 15)][(lane >> 4) * 8]);
    #pragma unroll
    for (int ni = 0; ni < 4; ni++)
        bAddr[ni] = smem_u32(&Bs[wn * 32 + ni * 8 + (lane & 7)][((lane >> 3) & 1) * 8]);

    for (int ch = 0; ch < 8; ch++) {
        __syncthreads();
        #pragma unroll
        for (int i = 0; i < 4; i++) {
            *(uint4*)&As[lrow][lcol + i * 8] = ra[i];
            *(uint4*)&Bs[lrow][lcol + i * 8] = rb[i];
        }
        __syncthreads();
        if (ch < 7) {
            const uint4* pa = (const uint4*)(srcA + (ch + 1) * BK);
            const uint4* pb = (const uint4*)(srcB + (ch + 1) * BK);
            #pragma unroll
            for (int i = 0; i < 4; i++) { ra[i] = pa[i]; rb[i] = pb[i]; }
        }
        #pragma unroll
        for (int ks = 0; ks < 4; ks++) {
            unsigned a[4][4], b[4][2];
            #pragma unroll
            for (int mi = 0; mi < 4; mi++)
                ldsm_x4(a[mi][0], a[mi][1], a[mi][2], a[mi][3], aAddr[mi] + ks * 32);
            #pragma unroll
            for (int ni = 0; ni < 4; ni++)
                ldsm_x2(b[ni][0], b[ni][1], bAddr[ni] + ks * 32);
            #pragma unroll
            for (int mi = 0; mi < 4; mi++)
                #pragma unroll
                for (int ni = 0; ni < 4; ni++)
                    hmma(acc[mi][ni], a[mi], b[ni]);
        }
    }

    const float* bias = b2 + e * H_DIM + colBase + wn * 32;
    int q  = lane & 3;
    int rr = lane >> 2;
    #pragma unroll
    for (int mi = 0; mi < 4; mi++) {
        #pragma unroll
        for (int h = 0; h < 2; h++) {
            int slot = row0 + wm * 64 + mi * 16 + rr + h * 8;
            if (slot < nt) {
                float cw = g_cw[e * T_TOK + slot];
                float* yrow = g_y + ((size_t)e * T_TOK + slot) * H_DIM
                            + colBase + wn * 32;
                #pragma unroll
                for (int ni = 0; ni < 4; ni++) {
                    float2 v;
                    v.x = cw * (acc[mi][ni][h * 2]     + bias[ni * 8 + q * 2]);
                    v.y = cw * (acc[mi][ni][h * 2 + 1] + bias[ni * 8 + q * 2 + 1]);
                    *(float2*)(yrow + ni * 8 + q * 2) = v;
                }
            }
        }
    }
}

// ---------------- combine: out = x + sum of 4 weighted expert rows ----------------
__global__ void combine_kernel(const float* __restrict__ x, float* __restrict__ out) {
    int t = blockIdx.x, tid = threadIdx.x;   // 128 threads, 4 floats each
    float4 acc = ((const float4*)(x + (size_t)t * H_DIM))[tid];
    #pragma unroll
    for (int k = 0; k < KTOP; k++) {
        int gs = g_slot[t * KTOP + k];
        float4 v = ((const float4*)(g_y + (size_t)gs * H_DIM))[tid];
        acc.x += v.x; acc.y += v.y; acc.z += v.z; acc.w += v.w;
    }
    ((float4*)(out + (size_t)t * H_DIM))[tid] = acc;
}

// ---------------- aux loss ----------------
__global__ void finalize_kernel(float* __restrict__ out, int out_size) {
    if (threadIdx.x == 0 && blockIdx.x == 0) {
        float load = 0.f;
        #pragma unroll
        for (int e = 0; e < E_NUM; e++) {
            float P = g_sumP[e] / (float)T_TOK;
            float D = g_wc[e] / (float)(T_TOK * KTOP);
            load += P * D;
        }
        load *= 0.01f * (float)E_NUM;
        float m = 0.f;
        #pragma unroll
        for (int e = 0; e < E_NUM; e++) m += g_imp[e];
        m *= (1.f / E_NUM);
        float v = 0.f;
        #pragma unroll
        for (int e = 0; e < E_NUM; e++) { float d = g_imp[e] - m; v += d * d; }
        v *= (1.f / (E_NUM - 1));
        float cv = sqrtf(v) / (m + 1e-6f);
        out[out_size - 1] = 1.0f * (load + 0.01f * cv * cv);
    }
}

// ---------------- launch ----------------
extern "C" void kernel_launch(void* const* d_in, const int* in_sizes, int n_in,
                              void* d_out, int out_size) {
    const float* x  = (const float*)d_in[0];
    const float* ns = (const float*)d_in[1];
    const float* gw = (const float*)d_in[2];
    const float* gb = (const float*)d_in[3];
    const float* w1 = (const float*)d_in[4];
    const float* b1 = (const float*)d_in[5];
    const float* w2 = (const float*)d_in[6];
    const float* b2 = (const float*)d_in[7];
    float* out = (float*)d_out;

    init_kernel<<<1, 32>>>();

    __half* w1h_ptr; cudaGetSymbolAddress((void**)&w1h_ptr, g_w1h);
    __half* w2h_ptr; cudaGetSymbolAddress((void**)&w2h_ptr, g_w2h);
    int n4_w1 = (E_NUM * 2 * I_DIM * H_DIM) / 4;   // 1,048,576
    int n4_w2 = (E_NUM * H_DIM * I_DIM) / 4;       //   524,288
    conv_kernel<<<(n4_w1 + 255) / 256, 256>>>(w1, w1h_ptr, n4_w1);
    conv_kernel<<<(n4_w2 + 255) / 256, 256>>>(w2, w2h_ptr, n4_w2);

    rmsnorm_kernel<<<T_TOK, 128>>>(x, ns);
    gate_kernel<<<T_TOK, 256>>>(gw, gb);

    dim3 g1(T_TOK / 128, (2 * I_DIM) / 128, E_NUM);   // 16 x 8 x 8
    gemm1_tc<<<g1, 256>>>(b1);
    dim3 g2(T_TOK / 128, H_DIM / 128, E_NUM);          // 16 x 4 x 8
    gemm2_tc<<<g2, 256>>>(b2);

    combine_kernel<<<T_TOK, 128>>>(x, out);
    finalize_kernel<<<1, 32>>>(out, out_size);
}

// round 9
// speedup vs baseline: 3.5267x; 1.0456x over previous
#include <cuda_runtime.h>
#include <cuda_fp16.h>
#include <math.h>

#define T_TOK 2048
#define H_DIM 512
#define I_DIM 512
#define E_NUM 8
#define KTOP  4
#define BK    64
#define KPAD  8
#define LDH   (BK + KPAD)                 // 72 halves = 144 B row stride
#define ATILE_BYTES (128 * LDH * 2)       // 18432
#define STAGE_BYTES (2 * ATILE_BYTES)     // A + B per stage = 36864
#define NSTAGE 3
#define SMEM_DYN (NSTAGE * STAGE_BYTES)   // 110592

// ---------------- scratch (device globals, no allocs) ----------------
__device__ __half g_th [T_TOK * H_DIM];                       // RMSNorm out fp16 (gemm1 A)
__device__ __half g_w1h[(size_t)E_NUM * 2 * I_DIM * H_DIM];   // W1 fp16
__device__ __half g_w2h[(size_t)E_NUM * H_DIM * I_DIM];       // W2 fp16
__device__ __half g_ah [(size_t)E_NUM * T_TOK * I_DIM];       // SwiGLU activations fp16
__device__ int    g_cnt[E_NUM];
__device__ int    g_tok[E_NUM * T_TOK];
__device__ float  g_cw [E_NUM * T_TOK];
__device__ float  g_sumP[E_NUM];
__device__ float  g_imp [E_NUM];
__device__ float  g_wc  [E_NUM];

// ---------------- PTX helpers (base compute_103 target: HMMA + LDSM + cp.async) ----------------
__device__ __forceinline__ unsigned smem_u32(const void* p) {
    unsigned r;
    asm("{ .reg .u64 t; cvta.to.shared.u64 t, %1; cvt.u32.u64 %0, t; }" : "=r"(r) : "l"(p));
    return r;
}
__device__ __forceinline__ void cp16(unsigned saddr, const void* gaddr) {
    asm volatile("cp.async.cg.shared.global [%0], [%1], 16;" :: "r"(saddr), "l"(gaddr));
}
__device__ __forceinline__ void cp_commit() {
    asm volatile("cp.async.commit_group;" ::: "memory");
}
__device__ __forceinline__ void ldsm_x4(unsigned& r0, unsigned& r1, unsigned& r2, unsigned& r3,
                                        unsigned addr) {
    asm volatile("ldmatrix.sync.aligned.m8n8.x4.shared.b16 {%0,%1,%2,%3}, [%4];"
                 : "=r"(r0), "=r"(r1), "=r"(r2), "=r"(r3) : "r"(addr));
}
__device__ __forceinline__ void ldsm_x2(unsigned& r0, unsigned& r1, unsigned addr) {
    asm volatile("ldmatrix.sync.aligned.m8n8.x2.shared.b16 {%0,%1}, [%2];"
                 : "=r"(r0), "=r"(r1) : "r"(addr));
}
__device__ __forceinline__ void hmma(float* c, const unsigned* a, const unsigned* b) {
    asm volatile("mma.sync.aligned.m16n8k16.row.col.f32.f16.f16.f32 "
                 "{%0,%1,%2,%3}, {%4,%5,%6,%7}, {%8,%9}, {%0,%1,%2,%3};"
                 : "+f"(c[0]), "+f"(c[1]), "+f"(c[2]), "+f"(c[3])
                 : "r"(a[0]), "r"(a[1]), "r"(a[2]), "r"(a[3]), "r"(b[0]), "r"(b[1]));
}

// ---------------- init: out = x (residual base for atomics), zero accumulators ----------------
__global__ void init_kernel(const float* __restrict__ x, float* __restrict__ out) {
    int i = blockIdx.x * blockDim.x + threadIdx.x;
    if (i < (T_TOK * H_DIM) / 4) ((float4*)out)[i] = ((const float4*)x)[i];
    if (blockIdx.x == 0 && threadIdx.x < E_NUM) {
        g_cnt[threadIdx.x]  = 0;
        g_sumP[threadIdx.x] = 0.f;
        g_imp[threadIdx.x]  = 0.f;
        g_wc[threadIdx.x]   = 0.f;
    }
}

// ---------------- fp32 -> fp16 weight conversion (both weights, one launch) ----------------
#define N4_W1 ((E_NUM * 2 * I_DIM * H_DIM) / 4)
#define N4_W2 ((E_NUM * H_DIM * I_DIM) / 4)
__global__ void conv_kernel(const float* __restrict__ w1, const float* __restrict__ w2) {
    int i = blockIdx.x * blockDim.x + threadIdx.x;
    const float* s; __half* d; int j;
    if (i < N4_W1)              { s = w1; d = g_w1h; j = i; }
    else if (i < N4_W1 + N4_W2) { s = w2; d = g_w2h; j = i - N4_W1; }
    else return;
    float4 v = ((const float4*)s)[j];
    ((__half2*)d)[2 * j]     = __floats2half2_rn(v.x, v.y);
    ((__half2*)d)[2 * j + 1] = __floats2half2_rn(v.z, v.w);
}

// ---------------- fused RMSNorm + gating ----------------
__global__ __launch_bounds__(256) void norm_gate_kernel(const float* __restrict__ x,
                                                        const float* __restrict__ ns,
                                                        const float* __restrict__ gw,
                                                        const float* __restrict__ gb) {
    int t = blockIdx.x, tid = threadIdx.x, w = tid >> 5, lane = tid & 31;
    __shared__ float ts[H_DIM];
    __shared__ float red[8];
    __shared__ float sl[E_NUM];

    float2 v = ((const float2*)(x + (size_t)t * H_DIM))[tid];
    float ss = v.x * v.x + v.y * v.y;
    #pragma unroll
    for (int o = 16; o; o >>= 1) ss += __shfl_xor_sync(0xffffffffu, ss, o);
    if (lane == 0) red[w] = ss;
    __syncthreads();
    float tot = 0.f;
    #pragma unroll
    for (int i = 0; i < 8; i++) tot += red[i];
    float r = rsqrtf(tot * (1.0f / H_DIM) + 1e-6f);
    float2 sc = ((const float2*)ns)[tid];
    float a = v.x * r * sc.x, b = v.y * r * sc.y;
    ts[2 * tid] = a; ts[2 * tid + 1] = b;
    ((__half2*)(g_th + (size_t)t * H_DIM))[tid] = __floats2half2_rn(a, b);
    __syncthreads();

    float s = 0.f;
    #pragma unroll
    for (int j = 0; j < H_DIM / 32; j++) s += ts[lane + 32 * j] * gw[w * H_DIM + lane + 32 * j];
    #pragma unroll
    for (int o = 16; o; o >>= 1) s += __shfl_xor_sync(0xffffffffu, s, o);
    if (lane == 0) sl[w] = s + gb[w];
    __syncthreads();
    if (tid == 0) {
        float l[E_NUM], p[E_NUM];
        float m = -1e30f;
        #pragma unroll
        for (int e = 0; e < E_NUM; e++) { l[e] = sl[e]; m = fmaxf(m, l[e]); }
        float sum = 0.f;
        #pragma unroll
        for (int e = 0; e < E_NUM; e++) { p[e] = expf(l[e] - m); sum += p[e]; }
        float inv = 1.f / sum;
        #pragma unroll
        for (int e = 0; e < E_NUM; e++) {
            p[e] *= inv;
            atomicAdd(&g_sumP[e], p[e]);
            atomicAdd(&g_imp[e],  l[e]);
        }
        bool used[E_NUM] = {false,false,false,false,false,false,false,false};
        int   idx[KTOP];  float wv[KTOP];  float wsum = 0.f;
        #pragma unroll
        for (int k = 0; k < KTOP; k++) {
            int best = -1; float bv = -1.f;
            #pragma unroll
            for (int e = 0; e < E_NUM; e++)
                if (!used[e] && p[e] > bv) { bv = p[e]; best = e; }
            used[best] = true; idx[k] = best; wv[k] = bv; wsum += bv;
            atomicAdd(&g_wc[best], (float)(16 >> k));
        }
        float winv = 1.f / wsum;
        #pragma unroll
        for (int k = 0; k < KTOP; k++) {
            int e = idx[k];
            int slot = atomicAdd(&g_cnt[e], 1);
            g_tok[e * T_TOK + slot] = t;
            g_cw [e * T_TOK + slot] = wv[k] * winv;
        }
    }
}

// ---------------- GEMM1 (mma.sync + cp.async x3): SwiGLU -> g_ah fp16 ----------------
// Block 128x128, K=512 in 8 chunks of 64. 8 warps (2m x 4n), warp tile 64x32.
__global__ __launch_bounds__(256) void gemm1_tc(const float* __restrict__ b1) {
    int e = blockIdx.z;
    int nt = g_cnt[e];
    int row0 = blockIdx.x * 128;
    if (row0 >= nt) return;
    int colBase = blockIdx.y * 128;                 // column in 2I space

    extern __shared__ __align__(16) unsigned char sm[];
    unsigned smBase = smem_u32(sm);

    int tid = threadIdx.x, lane = tid & 31, wid = tid >> 5;
    int wm = wid & 1, wn = wid >> 1;

    int lrow = tid >> 1;                            // 0..127
    int lcol = (tid & 1) * 32;
    const __half* srcA;
    const __half* srcB;
    {
        int slot = row0 + lrow; if (slot >= nt) slot = nt - 1;
        int token = g_tok[e * T_TOK + slot];
        srcA = g_th + (size_t)token * H_DIM + lcol;
        srcB = g_w1h + ((size_t)e * (2 * I_DIM) + colBase + lrow) * H_DIM + lcol;
    }
    unsigned stoff = (unsigned)(lrow * LDH + lcol) * 2;

    float acc[4][4][4];
    #pragma unroll
    for (int mi = 0; mi < 4; mi++)
        #pragma unroll
        for (int ni = 0; ni < 4; ni++)
            #pragma unroll
            for (int j = 0; j < 4; j++) acc[mi][ni][j] = 0.f;

    unsigned aRel[4], bRel[4];
    #pragma unroll
    for (int mi = 0; mi < 4; mi++)
        aRel[mi] = (unsigned)((wm * 64 + mi * 16 + (lane & 15)) * LDH + (lane >> 4) * 8) * 2;
    #pragma unroll
    for (int ni = 0; ni < 4; ni++)
        bRel[ni] = (unsigned)((wn * 32 + ni * 8 + (lane & 7)) * LDH + ((lane >> 3) & 1) * 8) * 2
                 + ATILE_BYTES;

    // prologue: chunk 0 -> stage 0
    {
        unsigned ab = smBase + stoff;
        #pragma unroll
        for (int i = 0; i < 4; i++) {
            cp16(ab + i * 16,               srcA + i * 8);
            cp16(ab + ATILE_BYTES + i * 16, srcB + i * 8);
        }
        cp_commit();
    }

    int st = 0;
    for (int ch = 0; ch < 8; ch++) {
        if (ch < 7) {
            int sn = st + 1; if (sn == NSTAGE) sn = 0;
            unsigned ab = smBase + sn * STAGE_BYTES + stoff;
            const __half* pa = srcA + (ch + 1) * BK;
            const __half* pb = srcB + (ch + 1) * BK;
            #pragma unroll
            for (int i = 0; i < 4; i++) {
                cp16(ab + i * 16,               pa + i * 8);
                cp16(ab + ATILE_BYTES + i * 16, pb + i * 8);
            }
            cp_commit();
            asm volatile("cp.async.wait_group 1;" ::: "memory");
        } else {
            asm volatile("cp.async.wait_group 0;" ::: "memory");
        }
        __syncthreads();

        unsigned sb = smBase + st * STAGE_BYTES;
        #pragma unroll
        for (int ks = 0; ks < 4; ks++) {
            unsigned a[4][4], b[4][2];
            #pragma unroll
            for (int mi = 0; mi < 4; mi++)
                ldsm_x4(a[mi][0], a[mi][1], a[mi][2], a[mi][3], sb + aRel[mi] + ks * 32);
            #pragma unroll
            for (int ni = 0; ni < 4; ni++)
                ldsm_x2(b[ni][0], b[ni][1], sb + bRel[ni] + ks * 32);
            #pragma unroll
            for (int mi = 0; mi < 4; mi++)
                #pragma unroll
                for (int ni = 0; ni < 4; ni++)
                    hmma(acc[mi][ni], a[mi], b[ni]);
        }
        if (++st == NSTAGE) st = 0;
    }

    // epilogue: fused bias + clip + SwiGLU (even/odd col pair lives in c0/c1)
    const float* bias = b1 + e * (2 * I_DIM) + colBase + wn * 32;
    int q  = lane & 3;
    int rr = lane >> 2;
    #pragma unroll
    for (int mi = 0; mi < 4; mi++) {
        #pragma unroll
        for (int h = 0; h < 2; h++) {
            int slot = row0 + wm * 64 + mi * 16 + rr + h * 8;
            if (slot < nt) {
                __half* arow = g_ah + ((size_t)e * T_TOK + slot) * I_DIM
                             + (colBase >> 1) + wn * 16;
                #pragma unroll
                for (int ni = 0; ni < 4; ni++) {
                    float hg = acc[mi][ni][h * 2]     + bias[ni * 8 + q * 2];
                    float hl = acc[mi][ni][h * 2 + 1] + bias[ni * 8 + q * 2 + 1];
                    hg = fminf(fmaxf(hg, -7.f), 7.f);
                    hl = fminf(fmaxf(hl, -7.f), 7.f);
                    float sg = 1.f / (1.f + __expf(-1.702f * hg));
                    arow[ni * 4 + q] = __float2half_rn(hg * sg + (hl + 1.f));
                }
            }
        }
    }
}

// ---------------- GEMM2 (mma.sync + cp.async x3): out += cw*(a@W2^T + b2) ----------------
__global__ __launch_bounds__(256) void gemm2_tc(const float* __restrict__ b2,
                                                float* __restrict__ out) {
    int e = blockIdx.z;
    int nt = g_cnt[e];
    int row0 = blockIdx.x * 128;
    if (row0 >= nt) return;
    int colBase = blockIdx.y * 128;                 // column in H space

    extern __shared__ __align__(16) unsigned char sm[];
    unsigned smBase = smem_u32(sm);

    int tid = threadIdx.x, lane = tid & 31, wid = tid >> 5;
    int wm = wid & 1, wn = wid >> 1;

    int lrow = tid >> 1;
    int lcol = (tid & 1) * 32;
    const __half* srcA;
    const __half* srcB;
    {
        int slot = row0 + lrow; if (slot >= nt) slot = nt - 1;
        srcA = g_ah + ((size_t)e * T_TOK + slot) * I_DIM + lcol;
        srcB = g_w2h + ((size_t)e * H_DIM + colBase + lrow) * I_DIM + lcol;
    }
    unsigned stoff = (unsigned)(lrow * LDH + lcol) * 2;

    float acc[4][4][4];
    #pragma unroll
    for (int mi = 0; mi < 4; mi++)
        #pragma unroll
        for (int ni = 0; ni < 4; ni++)
            #pragma unroll
            for (int j = 0; j < 4; j++) acc[mi][ni][j] = 0.f;

    unsigned aRel[4], bRel[4];
    #pragma unroll
    for (int mi = 0; mi < 4; mi++)
        aRel[mi] = (unsigned)((wm * 64 + mi * 16 + (lane & 15)) * LDH + (lane >> 4) * 8) * 2;
    #pragma unroll
    for (int ni = 0; ni < 4; ni++)
        bRel[ni] = (unsigned)((wn * 32 + ni * 8 + (lane & 7)) * LDH + ((lane >> 3) & 1) * 8) * 2
                 + ATILE_BYTES;

    {
        unsigned ab = smBase + stoff;
        #pragma unroll
        for (int i = 0; i < 4; i++) {
            cp16(ab + i * 16,               srcA + i * 8);
            cp16(ab + ATILE_BYTES + i * 16, srcB + i * 8);
        }
        cp_commit();
    }

    int st = 0;
    for (int ch = 0; ch < 8; ch++) {
        if (ch < 7) {
            int sn = st + 1; if (sn == NSTAGE) sn = 0;
            unsigned ab = smBase + sn * STAGE_BYTES + stoff;
            const __half* pa = srcA + (ch + 1) * BK;
            const __half* pb = srcB + (ch + 1) * BK;
            #pragma unroll
            for (int i = 0; i < 4; i++) {
                cp16(ab + i * 16,               pa + i * 8);
                cp16(ab + ATILE_BYTES + i * 16, pb + i * 8);
            }
            cp_commit();
            asm volatile("cp.async.wait_group 1;" ::: "memory");
        } else {
            asm volatile("cp.async.wait_group 0;" ::: "memory");
        }
        __syncthreads();

        unsigned sb = smBase + st * STAGE_BYTES;
        #pragma unroll
        for (int ks = 0; ks < 4; ks++) {
            unsigned a[4][4], b[4][2];
            #pragma unroll
            for (int mi = 0; mi < 4; mi++)
                ldsm_x4(a[mi][0], a[mi][1], a[mi][2], a[mi][3], sb + aRel[mi] + ks * 32);
            #pragma unroll
            for (int ni = 0; ni < 4; ni++)
                ldsm_x2(b[ni][0], b[ni][1], sb + bRel[ni] + ks * 32);
            #pragma unroll
            for (int mi = 0; mi < 4; mi++)
                #pragma unroll
                for (int ni = 0; ni < 4; ni++)
                    hmma(acc[mi][ni], a[mi], b[ni]);
        }
        if (++st == NSTAGE) st = 0;
    }

    const float* bias = b2 + e * H_DIM + colBase + wn * 32;
    int q  = lane & 3;
    int rr = lane >> 2;
    #pragma unroll
    for (int mi = 0; mi < 4; mi++) {
        #pragma unroll
        for (int h = 0; h < 2; h++) {
            int slot = row0 + wm * 64 + mi * 16 + rr + h * 8;
            if (slot < nt) {
                int token = g_tok[e * T_TOK + slot];
                float cw  = g_cw [e * T_TOK + slot];
                float* orow = out + (size_t)token * H_DIM + colBase + wn * 32;
                #pragma unroll
                for (int ni = 0; ni < 4; ni++) {
                    atomicAdd(&orow[ni * 8 + q * 2],
                              cw * (acc[mi][ni][h * 2]     + bias[ni * 8 + q * 2]));
                    atomicAdd(&orow[ni * 8 + q * 2 + 1],
                              cw * (acc[mi][ni][h * 2 + 1] + bias[ni * 8 + q * 2 + 1]));
                }
            }
        }
    }
}

// ---------------- aux loss ----------------
__global__ void finalize_kernel(float* __restrict__ out, int out_size) {
    if (threadIdx.x == 0 && blockIdx.x == 0) {
        float load = 0.f;
        #pragma unroll
        for (int e = 0; e < E_NUM; e++) {
            float P = g_sumP[e] / (float)T_TOK;
            float D = g_wc[e] / (float)(T_TOK * KTOP);
            load += P * D;
        }
        load *= 0.01f * (float)E_NUM;
        float m = 0.f;
        #pragma unroll
        for (int e = 0; e < E_NUM; e++) m += g_imp[e];
        m *= (1.f / E_NUM);
        float v = 0.f;
        #pragma unroll
        for (int e = 0; e < E_NUM; e++) { float d = g_imp[e] - m; v += d * d; }
        v *= (1.f / (E_NUM - 1));
        float cv = sqrtf(v) / (m + 1e-6f);
        out[out_size - 1] = 1.0f * (load + 0.01f * cv * cv);
    }
}

// ---------------- launch ----------------
extern "C" void kernel_launch(void* const* d_in, const int* in_sizes, int n_in,
                              void* d_out, int out_size) {
    const float* x  = (const float*)d_in[0];
    const float* ns = (const float*)d_in[1];
    const float* gw = (const float*)d_in[2];
    const float* gb = (const float*)d_in[3];
    const float* w1 = (const float*)d_in[4];
    const float* b1 = (const float*)d_in[5];
    const float* w2 = (const float*)d_in[6];
    const float* b2 = (const float*)d_in[7];
    float* out = (float*)d_out;

    static int smem_set = 0;
    if (!smem_set) {
        cudaFuncSetAttribute(gemm1_tc, cudaFuncAttributeMaxDynamicSharedMemorySize, SMEM_DYN);
        cudaFuncSetAttribute(gemm2_tc, cudaFuncAttributeMaxDynamicSharedMemorySize, SMEM_DYN);
        smem_set = 1;
    }

    init_kernel<<<(T_TOK * H_DIM / 4 + 255) / 256, 256>>>(x, out);
    conv_kernel<<<(N4_W1 + N4_W2 + 255) / 256, 256>>>(w1, w2);
    norm_gate_kernel<<<T_TOK, 256>>>(x, ns, gw, gb);

    dim3 g1(T_TOK / 128, (2 * I_DIM) / 128, E_NUM);   // 16 x 8 x 8
    gemm1_tc<<<g1, 256, SMEM_DYN>>>(b1);
    dim3 g2(T_TOK / 128, H_DIM / 128, E_NUM);          // 16 x 4 x 8
    gemm2_tc<<<g2, 256, SMEM_DYN>>>(b2, out);

    finalize_kernel<<<1, 32>>>(out, out_size);
}